// round 3
// baseline (speedup 1.0000x reference)
#include <cuda_runtime.h>
#include <math.h>

#define NN 100000
#define EE 1600000
#define GG 1000
#define HH 64
#define CC 10
#define BN_EPS 1e-5f

// ---------------- scratch (static device memory; no allocation at runtime) ----
__device__ __align__(16) int   g_cnt[NN];        // in-degree (without self loop)
__device__ __align__(16) int   g_off[NN + 1];    // CSR row offsets
__device__ __align__(16) int   g_cur[NN];        // fill cursors
__device__ __align__(16) int   g_srcs[EE];       // CSR column (src) ids
__device__ __align__(16) float g_dis[NN];        // deg^{-1/2} (incl. self loop)
__device__ __align__(16) float g_t[NN * HH];     // transformed features (h @ W + b)
__device__ __align__(16) float g_h[NN * HH];     // conv1 output / hidden
__device__ __align__(16) float g_bn[256];        // [0:64] sum,[64:128] sumsq,[128:192] mu,[192:256] istd
__device__ __align__(16) float g_cbn[256];       // same for classifier BN
__device__ __align__(16) float g_gsum[GG * HH];  // per-graph feature sums
__device__ __align__(16) float g_gcnt[GG];       // per-graph node counts
__device__ __align__(16) float g_z1[GG * HH];    // classifier hidden pre-BN
__device__ __align__(16) int   g_bsum[128];      // scan block sums (98 used)

// ---------------- zero scratch ------------------------------------------------
__global__ void k_zero() {
    int i = blockIdx.x * blockDim.x + threadIdx.x;
    if (i < NN) g_cnt[i] = 0;
    if (i < 256) { g_bn[i] = 0.f; g_cbn[i] = 0.f; }
    if (i < GG * HH) g_gsum[i] = 0.f;
    if (i < GG) g_gcnt[i] = 0.f;
}

// ---------------- degree count (edge_index is INT32: (2,E) row-major) --------
__global__ void k_degree(const int* __restrict__ ei) {
    int e = blockIdx.x * blockDim.x + threadIdx.x;
    if (e >= EE) return;
    int d = ei[EE + e];
    atomicAdd(&g_cnt[d], 1);
}

// ---------------- exclusive scan of g_cnt -> g_off ----------------------------
__global__ void k_scan_block() {
    __shared__ int s[1024];
    int tid = threadIdx.x;
    int i = blockIdx.x * 1024 + tid;
    int v = (i < NN) ? g_cnt[i] : 0;
    s[tid] = v;
    __syncthreads();
    #pragma unroll
    for (int d = 1; d < 1024; d <<= 1) {
        int add = (tid >= d) ? s[tid - d] : 0;
        __syncthreads();
        s[tid] += add;
        __syncthreads();
    }
    if (i < NN) g_off[i] = s[tid] - v;          // exclusive within block
    if (tid == 0) g_bsum[blockIdx.x] = s[1023]; // block total
}

__global__ void k_scan_top(int nb) {
    __shared__ int s[128];
    int tid = threadIdx.x;
    int v = (tid < nb) ? g_bsum[tid] : 0;
    s[tid] = v;
    __syncthreads();
    #pragma unroll
    for (int d = 1; d < 128; d <<= 1) {
        int add = (tid >= d) ? s[tid - d] : 0;
        __syncthreads();
        s[tid] += add;
        __syncthreads();
    }
    g_bsum[tid] = s[tid] - v;                   // exclusive base per block
}

__global__ void k_scan_add() {
    int i = blockIdx.x * blockDim.x + threadIdx.x;
    if (i >= NN) return;
    int o = g_off[i] + g_bsum[i >> 10];
    g_off[i] = o;
    g_cur[i] = o;
    g_dis[i] = rsqrtf((float)(g_cnt[i] + 1));
    if (i == 0) g_off[NN] = EE;
}

// ---------------- CSR fill ----------------------------------------------------
__global__ void k_fill(const int* __restrict__ ei) {
    int e = blockIdx.x * blockDim.x + threadIdx.x;
    if (e >= EE) return;
    int s = ei[e];
    int d = ei[EE + e];
    int pos = atomicAdd(&g_cur[d], 1);
    g_srcs[pos] = s;
}

// ---------------- dense 64x64 transform: out = in @ W + b ---------------------
__device__ __forceinline__ void gemm64_body(const float* __restrict__ in,
                                            const float* __restrict__ W,
                                            const float* __restrict__ bias,
                                            float* __restrict__ out, int n) {
    __shared__ __align__(16) float Wsh[64 * 64];
    __shared__ float bsh[64];
    __shared__ float xsh[8][64];
    int tid = threadIdx.x;
    for (int i = tid; i < 4096; i += 256) Wsh[i] = W[i];
    if (tid < 64) bsh[tid] = bias[tid];
    __syncthreads();
    int warp = tid >> 5, lane = tid & 31;
    int step = gridDim.x * 8;
    for (int r = blockIdx.x * 8 + warp; r < n; r += step) {
        float2 xv = *(const float2*)(in + (size_t)r * 64 + 2 * lane);
        xsh[warp][2 * lane] = xv.x;
        xsh[warp][2 * lane + 1] = xv.y;
        __syncwarp();
        float ax = bsh[2 * lane], ay = bsh[2 * lane + 1];
        #pragma unroll
        for (int k = 0; k < 64; k++) {
            float xk = xsh[warp][k];
            float2 w = *(const float2*)&Wsh[k * 64 + 2 * lane];
            ax += xk * w.x;
            ay += xk * w.y;
        }
        __syncwarp();
        *(float2*)(out + (size_t)r * 64 + 2 * lane) = make_float2(ax, ay);
    }
}

__global__ void k_gemm_x_to_t(const float* __restrict__ x, const float* __restrict__ W,
                              const float* __restrict__ bias) {
    gemm64_body(x, W, bias, g_t, NN);
}

__global__ void k_gemm_h_to_t(const float* __restrict__ W, const float* __restrict__ bias) {
    gemm64_body(g_h, W, bias, g_t, NN);
}

// ---------------- aggregate: out[v] = dis[v]*(sum dis[s]*t[s] + dis[v]*t[v]) --
__device__ __forceinline__ void agg_row(int v, int lane, float& sx, float& sy) {
    const float* __restrict__ t = g_t;
    int beg = g_off[v], end = g_off[v + 1];
    sx = 0.f; sy = 0.f;
    int e = beg;
    for (; e + 4 <= end; e += 4) {
        int s0 = g_srcs[e], s1 = g_srcs[e + 1], s2 = g_srcs[e + 2], s3 = g_srcs[e + 3];
        float w0 = g_dis[s0], w1 = g_dis[s1], w2 = g_dis[s2], w3 = g_dis[s3];
        float2 a0 = *(const float2*)(t + (size_t)s0 * 64 + 2 * lane);
        float2 a1 = *(const float2*)(t + (size_t)s1 * 64 + 2 * lane);
        float2 a2 = *(const float2*)(t + (size_t)s2 * 64 + 2 * lane);
        float2 a3 = *(const float2*)(t + (size_t)s3 * 64 + 2 * lane);
        sx += w0 * a0.x + w1 * a1.x + w2 * a2.x + w3 * a3.x;
        sy += w0 * a0.y + w1 * a1.y + w2 * a2.y + w3 * a3.y;
    }
    for (; e < end; e++) {
        int s = g_srcs[e];
        float w = g_dis[s];
        float2 a = *(const float2*)(t + (size_t)s * 64 + 2 * lane);
        sx += w * a.x;
        sy += w * a.y;
    }
    float dv = g_dis[v];
    float2 self = *(const float2*)(t + (size_t)v * 64 + 2 * lane);
    sx = dv * (sx + dv * self.x);
    sy = dv * (sy + dv * self.y);
}

__global__ void k_agg_store() {
    int warp = (blockIdx.x * blockDim.x + threadIdx.x) >> 5;
    int lane = threadIdx.x & 31;
    if (warp >= NN) return;
    float sx, sy;
    agg_row(warp, lane, sx, sy);
    *(float2*)(g_h + (size_t)warp * 64 + 2 * lane) = make_float2(sx, sy);
}

__global__ void k_agg_pool(const int* __restrict__ batch) {
    int warp = (blockIdx.x * blockDim.x + threadIdx.x) >> 5;
    int lane = threadIdx.x & 31;
    if (warp >= NN) return;
    float sx, sy;
    agg_row(warp, lane, sx, sy);
    int g = batch[warp];
    atomicAdd(&g_gsum[g * 64 + 2 * lane], sx);
    atomicAdd(&g_gsum[g * 64 + 2 * lane + 1], sy);
    if (lane == 0) atomicAdd(&g_gcnt[g], 1.0f);
}

// ---------------- batch-norm stats / finalize / apply -------------------------
__global__ void k_bnstats() {
    __shared__ float ssum[256], ssq[256];
    int tid = threadIdx.x;
    int c = tid & 63;
    int rlane = tid >> 6;  // 0..3
    float s = 0.f, q = 0.f;
    for (int r = blockIdx.x * 4 + rlane; r < NN; r += gridDim.x * 4) {
        float x = g_h[(size_t)r * 64 + c];
        s += x;
        q += x * x;
    }
    ssum[tid] = s; ssq[tid] = q;
    __syncthreads();
    if (tid < 64) {
        s = ssum[tid] + ssum[tid + 64] + ssum[tid + 128] + ssum[tid + 192];
        q = ssq[tid] + ssq[tid + 64] + ssq[tid + 128] + ssq[tid + 192];
        atomicAdd(&g_bn[tid], s);
        atomicAdd(&g_bn[64 + tid], q);
    }
}

__global__ void k_bnfinal(int which, float count) {
    float* accum = which ? g_cbn : g_bn;
    int c = threadIdx.x;
    float mu = accum[c] / count;
    float var = accum[64 + c] / count - mu * mu;
    accum[128 + c] = mu;
    accum[192 + c] = rsqrtf(var + BN_EPS);
}

__global__ void k_bnrelu(const float* __restrict__ gamma, const float* __restrict__ beta) {
    int i = blockIdx.x * blockDim.x + threadIdx.x;
    if (i >= NN * HH) return;
    int c = i & 63;
    float x = (g_h[i] - g_bn[128 + c]) * g_bn[192 + c] * gamma[c] + beta[c];
    g_h[i] = fmaxf(x, 0.f);
}

// ---------------- graph-level: pool finalize + L2 norm + Wc1 ------------------
__global__ void k_graph1(const float* __restrict__ Wc1, const float* __restrict__ bc1,
                         float* __restrict__ rep_out) {
    __shared__ __align__(16) float Wsh[64 * 64];
    __shared__ float bsh[64];
    __shared__ float xsh[8][64];
    int tid = threadIdx.x;
    for (int i = tid; i < 4096; i += 256) Wsh[i] = Wc1[i];
    if (tid < 64) bsh[tid] = bc1[tid];
    __syncthreads();
    int warp = tid >> 5, lane = tid & 31;
    int g = blockIdx.x * 8 + warp;
    if (g >= GG) return;
    float cnt = fmaxf(g_gcnt[g], 1.0f);
    float mx = g_gsum[g * 64 + 2 * lane] / cnt;
    float my = g_gsum[g * 64 + 2 * lane + 1] / cnt;
    float ss = mx * mx + my * my;
    #pragma unroll
    for (int o = 16; o > 0; o >>= 1) ss += __shfl_xor_sync(0xffffffff, ss, o);
    float inv = rsqrtf(ss);
    mx *= inv; my *= inv;
    rep_out[g * 64 + 2 * lane] = mx;
    rep_out[g * 64 + 2 * lane + 1] = my;
    xsh[warp][2 * lane] = mx;
    xsh[warp][2 * lane + 1] = my;
    __syncwarp();
    float ax = bsh[2 * lane], ay = bsh[2 * lane + 1];
    #pragma unroll
    for (int k = 0; k < 64; k++) {
        float xk = xsh[warp][k];
        float2 w = *(const float2*)&Wsh[k * 64 + 2 * lane];
        ax += xk * w.x;
        ay += xk * w.y;
    }
    g_z1[g * 64 + 2 * lane] = ax;
    g_z1[g * 64 + 2 * lane + 1] = ay;
    atomicAdd(&g_cbn[2 * lane], ax);
    atomicAdd(&g_cbn[2 * lane + 1], ay);
    atomicAdd(&g_cbn[64 + 2 * lane], ax * ax);
    atomicAdd(&g_cbn[64 + 2 * lane + 1], ay * ay);
}

// ---------------- classifier tail: BN+ReLU -> Wc2 -> log_softmax --------------
__global__ void k_graph2(const float* __restrict__ Wc2, const float* __restrict__ bc2,
                         const float* __restrict__ gammac, const float* __restrict__ betac,
                         float* __restrict__ pred_out) {
    __shared__ float Wsh[64 * 10];
    __shared__ float xsh[8][64];
    int tid = threadIdx.x;
    for (int i = tid; i < 640; i += 256) Wsh[i] = Wc2[i];
    __syncthreads();
    int warp = tid >> 5, lane = tid & 31;
    int g = blockIdx.x * 8 + warp;
    if (g >= GG) return;
    int c0 = 2 * lane, c1 = 2 * lane + 1;
    float z0 = g_z1[g * 64 + c0];
    float z1v = g_z1[g * 64 + c1];
    z0 = fmaxf((z0 - g_cbn[128 + c0]) * g_cbn[192 + c0] * gammac[c0] + betac[c0], 0.f);
    z1v = fmaxf((z1v - g_cbn[128 + c1]) * g_cbn[192 + c1] * gammac[c1] + betac[c1], 0.f);
    xsh[warp][c0] = z0;
    xsh[warp][c1] = z1v;
    __syncwarp();
    bool valid = (lane < CC);
    float acc = valid ? bc2[lane] : 0.f;
    if (valid) {
        #pragma unroll
        for (int k = 0; k < 64; k++) acc += xsh[warp][k] * Wsh[k * 10 + lane];
    }
    float v = valid ? acc : -1e30f;
    float m = v;
    #pragma unroll
    for (int o = 16; o > 0; o >>= 1) m = fmaxf(m, __shfl_xor_sync(0xffffffff, m, o));
    float ex = valid ? __expf(v - m) : 0.f;
    float s = ex;
    #pragma unroll
    for (int o = 16; o > 0; o >>= 1) s += __shfl_xor_sync(0xffffffff, s, o);
    if (valid) pred_out[g * CC + lane] = v - m - logf(s);
}

// ---------------- launch ------------------------------------------------------
extern "C" void kernel_launch(void* const* d_in, const int* in_sizes, int n_in,
                              void* d_out, int out_size) {
    const float* x     = (const float*)d_in[0];
    const int*   ei    = (const int*)d_in[1];    // int32! (JAX x64 disabled)
    const int*   batch = (const int*)d_in[2];    // int32!
    const float* W1    = (const float*)d_in[3];
    const float* b1    = (const float*)d_in[4];
    const float* gamma1= (const float*)d_in[5];
    const float* beta1 = (const float*)d_in[6];
    const float* W2    = (const float*)d_in[7];
    const float* b2    = (const float*)d_in[8];
    const float* Wc1   = (const float*)d_in[9];
    const float* bc1   = (const float*)d_in[10];
    const float* gammac= (const float*)d_in[11];
    const float* betac = (const float*)d_in[12];
    const float* Wc2   = (const float*)d_in[13];
    const float* bc2   = (const float*)d_in[14];

    float* out  = (float*)d_out;
    float* pred = out;              // [G, 10]
    float* rep  = out + GG * CC;    // [G, 64]

    const int nb_scan = (NN + 1023) / 1024;  // 98

    k_zero<<<(NN + 255) / 256, 256>>>();
    k_degree<<<(EE + 255) / 256, 256>>>(ei);
    k_scan_block<<<nb_scan, 1024>>>();
    k_scan_top<<<1, 128>>>(nb_scan);
    k_scan_add<<<(NN + 255) / 256, 256>>>();
    k_fill<<<(EE + 255) / 256, 256>>>(ei);

    // conv1: transform -> aggregate -> BN -> ReLU
    k_gemm_x_to_t<<<1184, 256>>>(x, W1, b1);
    k_agg_store<<<(NN + 7) / 8, 256>>>();
    k_bnstats<<<1184, 256>>>();
    k_bnfinal<<<1, 64>>>(0, (float)NN);
    k_bnrelu<<<(NN * HH + 255) / 256, 256>>>(gamma1, beta1);

    // conv2: transform -> aggregate fused with graph pooling
    k_gemm_h_to_t<<<1184, 256>>>(W2, b2);
    k_agg_pool<<<(NN + 7) / 8, 256>>>(batch);

    // classifier
    k_graph1<<<(GG + 7) / 8, 256>>>(Wc1, bc1, rep);
    k_bnfinal<<<1, 64>>>(1, (float)GG);
    k_graph2<<<(GG + 7) / 8, 256>>>(Wc2, bc2, gammac, betac, pred);
}

// round 6
// speedup vs baseline: 1.0449x; 1.0449x over previous
#include <cuda_runtime.h>
#include <cuda_fp16.h>
#include <math.h>

#define NN 100000
#define EE 1600000
#define GG 1000
#define HH 64
#define CC 10
#define BN_EPS 1e-5f

// ---------------- scratch (static device memory; no allocation at runtime) ----
__device__ __align__(16) int    g_cnt[NN];        // in-degree (without self loop)
__device__ __align__(16) int    g_off[NN + 1];    // CSR row offsets
__device__ __align__(16) int    g_cur[NN];        // fill cursors
__device__ __align__(16) int    g_srcs[EE];       // CSR column (src) ids
__device__ __align__(16) float  g_dis[NN];        // deg^{-1/2} (incl. self loop)
__device__ __align__(16) __half g_t[NN * HH];     // transformed features, fp16
__device__ __align__(16) float  g_h[NN * HH];     // conv1 output / hidden (fp32)
__device__ __align__(16) float  g_bn[256];        // [0:64] sum,[64:128] sumsq,[128:192] mu,[192:256] istd
__device__ __align__(16) float  g_cbn[256];       // same for classifier BN
__device__ __align__(16) float  g_gsum[GG * HH];  // per-graph feature sums
__device__ __align__(16) float  g_gcnt[GG];       // per-graph node counts
__device__ __align__(16) float  g_z1[GG * HH];    // classifier hidden pre-BN
__device__ __align__(16) int    g_bsum[128];      // scan block sums (98 used)

// ---------------- zero scratch ------------------------------------------------
__global__ void k_zero() {
    int i = blockIdx.x * blockDim.x + threadIdx.x;
    if (i < NN) g_cnt[i] = 0;
    if (i < 256) { g_bn[i] = 0.f; g_cbn[i] = 0.f; }
    if (i < GG * HH) g_gsum[i] = 0.f;
    if (i < GG) g_gcnt[i] = 0.f;
}

// ---------------- degree count (edge_index is INT32: (2,E) row-major) --------
__global__ void k_degree(const int* __restrict__ ei) {
    int e = blockIdx.x * blockDim.x + threadIdx.x;
    if (e >= EE) return;
    int d = ei[EE + e];
    atomicAdd(&g_cnt[d], 1);
}

// ---------------- exclusive scan of g_cnt -> g_off (warp-shuffle based) -------
__global__ void k_scan_block() {
    __shared__ int wsum[32];
    int tid = threadIdx.x;
    int lane = tid & 31, warp = tid >> 5;
    int i = blockIdx.x * 1024 + tid;
    int v = (i < NN) ? g_cnt[i] : 0;
    int x = v;
    #pragma unroll
    for (int d = 1; d < 32; d <<= 1) {
        int n = __shfl_up_sync(0xffffffff, x, d);
        if (lane >= d) x += n;
    }
    if (lane == 31) wsum[warp] = x;
    __syncthreads();
    if (warp == 0) {
        int y = wsum[lane];
        #pragma unroll
        for (int d = 1; d < 32; d <<= 1) {
            int n = __shfl_up_sync(0xffffffff, y, d);
            if (lane >= d) y += n;
        }
        wsum[lane] = y;
    }
    __syncthreads();
    int base = warp ? wsum[warp - 1] : 0;
    int incl = base + x;
    if (i < NN) g_off[i] = incl - v;               // exclusive within block
    if (tid == 1023) g_bsum[blockIdx.x] = incl;    // block total
}

__global__ void k_scan_top(int nb) {
    __shared__ int wsum[4];
    int tid = threadIdx.x;
    int lane = tid & 31, warp = tid >> 5;
    int v = (tid < nb) ? g_bsum[tid] : 0;
    int x = v;
    #pragma unroll
    for (int d = 1; d < 32; d <<= 1) {
        int n = __shfl_up_sync(0xffffffff, x, d);
        if (lane >= d) x += n;
    }
    if (lane == 31) wsum[warp] = x;
    __syncthreads();
    if (warp == 0 && lane < 4) {
        int y = wsum[lane];
        #pragma unroll
        for (int d = 1; d < 4; d <<= 1) {
            int n = __shfl_up_sync(0x0000000f, y, d);
            if (lane >= d) y += n;
        }
        wsum[lane] = y;
    }
    __syncthreads();
    int base = warp ? wsum[warp - 1] : 0;
    g_bsum[tid] = base + x - v;                    // exclusive base per block
}

__global__ void k_scan_add() {
    int i = blockIdx.x * blockDim.x + threadIdx.x;
    if (i >= NN) return;
    int o = g_off[i] + g_bsum[i >> 10];
    g_off[i] = o;
    g_cur[i] = o;
    g_dis[i] = rsqrtf((float)(g_cnt[i] + 1));
    if (i == 0) g_off[NN] = EE;
}

// ---------------- CSR fill ----------------------------------------------------
__global__ void k_fill(const int* __restrict__ ei) {
    int e = blockIdx.x * blockDim.x + threadIdx.x;
    if (e >= EE) return;
    int s = ei[e];
    int d = ei[EE + e];
    int pos = atomicAdd(&g_cur[d], 1);
    g_srcs[pos] = s;
}

// ---- dense 64x64 transform: g_t(half) = [BN+ReLU](src) @ W + b ---------------
// MODE 0: src = x (harness input pointer), no BN
// MODE 1: src = g_h (device symbol, accessed only from device code), fused BN+ReLU
template <int MODE>
__global__ void k_gemm(const float* __restrict__ in, const float* __restrict__ W,
                       const float* __restrict__ bias,
                       const float* __restrict__ gamma, const float* __restrict__ beta) {
    __shared__ __align__(16) float Wsh[64 * 64];
    __shared__ float bsh[64];
    __shared__ float xsh[8][64];
    int tid = threadIdx.x;
    for (int i = tid; i < 4096; i += 256) Wsh[i] = W[i];
    if (tid < 64) bsh[tid] = bias[tid];
    __syncthreads();
    int warp = tid >> 5, lane = tid & 31;
    int c0 = 2 * lane, c1 = c0 + 1;
    float a0 = 1.f, s0 = 0.f, a1 = 1.f, s1 = 0.f;
    if (MODE == 1) {
        float is0 = g_bn[192 + c0], is1 = g_bn[192 + c1];
        a0 = is0 * gamma[c0];
        a1 = is1 * gamma[c1];
        s0 = beta[c0] - g_bn[128 + c0] * a0;
        s1 = beta[c1] - g_bn[128 + c1] * a1;
    }
    const float* __restrict__ src = (MODE == 1) ? (const float*)g_h : in;
    __half2* outp = (__half2*)g_t;
    int step = gridDim.x * 8;
    for (int r = blockIdx.x * 8 + warp; r < NN; r += step) {
        float2 xv = *(const float2*)(src + (size_t)r * 64 + c0);
        if (MODE == 1) {
            xv.x = fmaxf(fmaf(xv.x, a0, s0), 0.f);
            xv.y = fmaxf(fmaf(xv.y, a1, s1), 0.f);
        }
        xsh[warp][c0] = xv.x;
        xsh[warp][c1] = xv.y;
        __syncwarp();
        float ax = bsh[c0], ay = bsh[c1];
        #pragma unroll
        for (int k = 0; k < 64; k++) {
            float xk = xsh[warp][k];
            float2 w = *(const float2*)&Wsh[k * 64 + c0];
            ax += xk * w.x;
            ay += xk * w.y;
        }
        __syncwarp();
        outp[r * 32 + lane] = __floats2half2_rn(ax, ay);
    }
}

// ---------------- aggregate: out[v] = dis[v]*(sum dis[s]*t[s] + dis[v]*t[v]) --
__device__ __forceinline__ void agg_row(int v, int lane, float& sx, float& sy) {
    const __half2* __restrict__ t = (const __half2*)g_t;
    int beg = g_off[v], end = g_off[v + 1];
    sx = 0.f; sy = 0.f;
    int e = beg;
    for (; e + 4 <= end; e += 4) {
        int s0 = g_srcs[e], s1 = g_srcs[e + 1], s2 = g_srcs[e + 2], s3 = g_srcs[e + 3];
        float w0 = g_dis[s0], w1 = g_dis[s1], w2 = g_dis[s2], w3 = g_dis[s3];
        float2 a0 = __half22float2(t[s0 * 32 + lane]);
        float2 a1 = __half22float2(t[s1 * 32 + lane]);
        float2 a2 = __half22float2(t[s2 * 32 + lane]);
        float2 a3 = __half22float2(t[s3 * 32 + lane]);
        sx += w0 * a0.x + w1 * a1.x + w2 * a2.x + w3 * a3.x;
        sy += w0 * a0.y + w1 * a1.y + w2 * a2.y + w3 * a3.y;
    }
    for (; e < end; e++) {
        int s = g_srcs[e];
        float w = g_dis[s];
        float2 a = __half22float2(t[s * 32 + lane]);
        sx += w * a.x;
        sy += w * a.y;
    }
    float dv = g_dis[v];
    float2 self = __half22float2(t[v * 32 + lane]);
    sx = dv * (sx + dv * self.x);
    sy = dv * (sy + dv * self.y);
}

// conv1 aggregate: write g_h AND accumulate BN statistics (fused)
__global__ void k_agg_bnstats() {
    __shared__ float ssum[8][64];
    __shared__ float ssq[8][64];
    int tid = threadIdx.x;
    int warp = tid >> 5, lane = tid & 31;
    int v = blockIdx.x * 8 + warp;
    int c0 = 2 * lane, c1 = c0 + 1;
    float sx = 0.f, sy = 0.f;
    if (v < NN) {
        agg_row(v, lane, sx, sy);
        *(float2*)(g_h + (size_t)v * 64 + c0) = make_float2(sx, sy);
    }
    ssum[warp][c0] = sx;  ssum[warp][c1] = sy;
    ssq[warp][c0] = sx * sx;  ssq[warp][c1] = sy * sy;
    __syncthreads();
    if (tid < 64) {
        float s = 0.f, q = 0.f;
        #pragma unroll
        for (int w = 0; w < 8; w++) { s += ssum[w][tid]; q += ssq[w][tid]; }
        atomicAdd(&g_bn[tid], s);
        atomicAdd(&g_bn[64 + tid], q);
    }
}

// conv2 aggregate fused with per-graph mean pooling
__global__ void k_agg_pool(const int* __restrict__ batch) {
    int warp = (blockIdx.x * blockDim.x + threadIdx.x) >> 5;
    int lane = threadIdx.x & 31;
    if (warp >= NN) return;
    float sx, sy;
    agg_row(warp, lane, sx, sy);
    int g = batch[warp];
    atomicAdd(&g_gsum[g * 64 + 2 * lane], sx);
    atomicAdd(&g_gsum[g * 64 + 2 * lane + 1], sy);
    if (lane == 0) atomicAdd(&g_gcnt[g], 1.0f);
}

// ---------------- batch-norm finalize -----------------------------------------
__global__ void k_bnfinal(int which, float count) {
    float* accum = which ? g_cbn : g_bn;
    int c = threadIdx.x;
    float mu = accum[c] / count;
    float var = accum[64 + c] / count - mu * mu;
    accum[128 + c] = mu;
    accum[192 + c] = rsqrtf(var + BN_EPS);
}

// ---------------- graph-level: pool finalize + L2 norm + Wc1 ------------------
__global__ void k_graph1(const float* __restrict__ Wc1, const float* __restrict__ bc1,
                         float* __restrict__ rep_out) {
    __shared__ __align__(16) float Wsh[64 * 64];
    __shared__ float bsh[64];
    __shared__ float xsh[8][64];
    int tid = threadIdx.x;
    for (int i = tid; i < 4096; i += 256) Wsh[i] = Wc1[i];
    if (tid < 64) bsh[tid] = bc1[tid];
    __syncthreads();
    int warp = tid >> 5, lane = tid & 31;
    int g = blockIdx.x * 8 + warp;
    if (g >= GG) return;
    float cnt = fmaxf(g_gcnt[g], 1.0f);
    float mx = g_gsum[g * 64 + 2 * lane] / cnt;
    float my = g_gsum[g * 64 + 2 * lane + 1] / cnt;
    float ss = mx * mx + my * my;
    #pragma unroll
    for (int o = 16; o > 0; o >>= 1) ss += __shfl_xor_sync(0xffffffff, ss, o);
    float inv = rsqrtf(ss);
    mx *= inv; my *= inv;
    rep_out[g * 64 + 2 * lane] = mx;
    rep_out[g * 64 + 2 * lane + 1] = my;
    xsh[warp][2 * lane] = mx;
    xsh[warp][2 * lane + 1] = my;
    __syncwarp();
    float ax = bsh[2 * lane], ay = bsh[2 * lane + 1];
    #pragma unroll
    for (int k = 0; k < 64; k++) {
        float xk = xsh[warp][k];
        float2 w = *(const float2*)&Wsh[k * 64 + 2 * lane];
        ax += xk * w.x;
        ay += xk * w.y;
    }
    g_z1[g * 64 + 2 * lane] = ax;
    g_z1[g * 64 + 2 * lane + 1] = ay;
    atomicAdd(&g_cbn[2 * lane], ax);
    atomicAdd(&g_cbn[2 * lane + 1], ay);
    atomicAdd(&g_cbn[64 + 2 * lane], ax * ax);
    atomicAdd(&g_cbn[64 + 2 * lane + 1], ay * ay);
}

// ---------------- classifier tail: BN+ReLU -> Wc2 -> log_softmax --------------
__global__ void k_graph2(const float* __restrict__ Wc2, const float* __restrict__ bc2,
                         const float* __restrict__ gammac, const float* __restrict__ betac,
                         float* __restrict__ pred_out) {
    __shared__ float Wsh[64 * 10];
    __shared__ float xsh[8][64];
    int tid = threadIdx.x;
    for (int i = tid; i < 640; i += 256) Wsh[i] = Wc2[i];
    __syncthreads();
    int warp = tid >> 5, lane = tid & 31;
    int g = blockIdx.x * 8 + warp;
    if (g >= GG) return;
    int c0 = 2 * lane, c1 = 2 * lane + 1;
    float z0 = g_z1[g * 64 + c0];
    float z1v = g_z1[g * 64 + c1];
    z0 = fmaxf((z0 - g_cbn[128 + c0]) * g_cbn[192 + c0] * gammac[c0] + betac[c0], 0.f);
    z1v = fmaxf((z1v - g_cbn[128 + c1]) * g_cbn[192 + c1] * gammac[c1] + betac[c1], 0.f);
    xsh[warp][c0] = z0;
    xsh[warp][c1] = z1v;
    __syncwarp();
    bool valid = (lane < CC);
    float acc = valid ? bc2[lane] : 0.f;
    if (valid) {
        #pragma unroll
        for (int k = 0; k < 64; k++) acc += xsh[warp][k] * Wsh[k * 10 + lane];
    }
    float v = valid ? acc : -1e30f;
    float m = v;
    #pragma unroll
    for (int o = 16; o > 0; o >>= 1) m = fmaxf(m, __shfl_xor_sync(0xffffffff, m, o));
    float ex = valid ? __expf(v - m) : 0.f;
    float s = ex;
    #pragma unroll
    for (int o = 16; o > 0; o >>= 1) s += __shfl_xor_sync(0xffffffff, s, o);
    if (valid) pred_out[g * CC + lane] = v - m - logf(s);
}

// ---------------- launch ------------------------------------------------------
extern "C" void kernel_launch(void* const* d_in, const int* in_sizes, int n_in,
                              void* d_out, int out_size) {
    const float* x     = (const float*)d_in[0];
    const int*   ei    = (const int*)d_in[1];    // int32 (JAX x64 disabled)
    const int*   batch = (const int*)d_in[2];    // int32
    const float* W1    = (const float*)d_in[3];
    const float* b1    = (const float*)d_in[4];
    const float* gamma1= (const float*)d_in[5];
    const float* beta1 = (const float*)d_in[6];
    const float* W2    = (const float*)d_in[7];
    const float* b2    = (const float*)d_in[8];
    const float* Wc1   = (const float*)d_in[9];
    const float* bc1   = (const float*)d_in[10];
    const float* gammac= (const float*)d_in[11];
    const float* betac = (const float*)d_in[12];
    const float* Wc2   = (const float*)d_in[13];
    const float* bc2   = (const float*)d_in[14];

    float* out  = (float*)d_out;
    float* pred = out;              // [G, 10]
    float* rep  = out + GG * CC;    // [G, 64]

    const int nb_scan = (NN + 1023) / 1024;  // 98

    k_zero<<<(NN + 255) / 256, 256>>>();
    k_degree<<<(EE + 255) / 256, 256>>>(ei);
    k_scan_block<<<nb_scan, 1024>>>();
    k_scan_top<<<1, 128>>>(nb_scan);
    k_scan_add<<<(NN + 255) / 256, 256>>>();
    k_fill<<<(EE + 255) / 256, 256>>>(ei);

    // conv1: transform(fp16 out) -> aggregate + BN stats -> BN finalize
    k_gemm<0><<<1184, 256>>>(x, W1, b1, nullptr, nullptr);
    k_agg_bnstats<<<(NN + 7) / 8, 256>>>();
    k_bnfinal<<<1, 64>>>(0, (float)NN);

    // conv2: BN+ReLU fused into transform (reads g_h internally) -> aggregate+pool
    k_gemm<1><<<1184, 256>>>(nullptr, W2, b2, gamma1, beta1);
    k_agg_pool<<<(NN + 7) / 8, 256>>>(batch);

    // classifier
    k_graph1<<<(GG + 7) / 8, 256>>>(Wc1, bc1, rep);
    k_bnfinal<<<1, 64>>>(1, (float)GG);
    k_graph2<<<(GG + 7) / 8, 256>>>(Wc2, bc2, gammac, betac, pred);
}

// round 7
// speedup vs baseline: 1.3983x; 1.3382x over previous
#include <cuda_runtime.h>
#include <cuda_fp16.h>
#include <math.h>

#define NN 100000
#define EE 1600000
#define GG 1000
#define HH 64
#define CC 10
#define BN_EPS 1e-5f

// ---------------- scratch (static device memory; no allocation at runtime) ----
__device__ __align__(16) int    g_cnt[NN];        // in-degree (without self loop)
__device__ __align__(16) int    g_off[NN + 1];    // CSR row offsets
__device__ __align__(16) int    g_cur[NN];        // fill cursors
__device__ __align__(16) int    g_srcs[EE];       // CSR column (src) ids
__device__ __align__(16) float  g_dis[NN];        // deg^{-1/2} (incl. self loop)
__device__ __align__(16) __half g_t[NN * HH];     // dis-scaled transformed features, fp16
__device__ __align__(16) float  g_h[NN * HH];     // conv1 output (fp32)
__device__ __align__(16) float  g_bn[128];        // [0:64] sum, [64:128] sumsq (conv1 BN)
__device__ __align__(16) float  g_cbn[128];       // same for classifier BN
__device__ __align__(16) float  g_gsum[GG * HH];  // per-graph feature sums
__device__ __align__(16) float  g_gcnt[GG];       // per-graph node counts
__device__ __align__(16) float  g_z1[GG * HH];    // classifier hidden pre-BN
__device__ __align__(16) int    g_bsum[128];      // scan block sums (98 used)

// ---------------- zero scratch ------------------------------------------------
__global__ void k_zero() {
    int i = blockIdx.x * blockDim.x + threadIdx.x;
    if (i < NN) g_cnt[i] = 0;
    if (i < 128) { g_bn[i] = 0.f; g_cbn[i] = 0.f; }
    if (i < GG * HH) g_gsum[i] = 0.f;
    if (i < GG) g_gcnt[i] = 0.f;
}

// ---------------- degree count (edge_index is INT32: (2,E) row-major) --------
__global__ void k_degree(const int* __restrict__ ei) {
    int e = blockIdx.x * blockDim.x + threadIdx.x;
    if (e >= EE) return;
    int d = ei[EE + e];
    atomicAdd(&g_cnt[d], 1);
}

// ---------------- block-level exclusive scan of g_cnt -------------------------
__global__ void k_scan_block() {
    __shared__ int wsum[32];
    int tid = threadIdx.x;
    int lane = tid & 31, warp = tid >> 5;
    int i = blockIdx.x * 1024 + tid;
    int v = (i < NN) ? g_cnt[i] : 0;
    int x = v;
    #pragma unroll
    for (int d = 1; d < 32; d <<= 1) {
        int n = __shfl_up_sync(0xffffffff, x, d);
        if (lane >= d) x += n;
    }
    if (lane == 31) wsum[warp] = x;
    __syncthreads();
    if (warp == 0) {
        int y = wsum[lane];
        #pragma unroll
        for (int d = 1; d < 32; d <<= 1) {
            int n = __shfl_up_sync(0xffffffff, y, d);
            if (lane >= d) y += n;
        }
        wsum[lane] = y;
    }
    __syncthreads();
    int base = warp ? wsum[warp - 1] : 0;
    int incl = base + x;
    if (i < NN) g_off[i] = incl - v;               // exclusive within block
    if (tid == 1023) g_bsum[blockIdx.x] = incl;    // block total
}

// ---- finalize offsets: each block redundantly scans the 98 block sums --------
__global__ void k_scan_add(int nb) {
    __shared__ int sbase[128];
    __shared__ int wtot[4];
    int tid = threadIdx.x;
    int lane = tid & 31, w = tid >> 5;
    int v = 0, x = 0;
    if (tid < 128) {
        v = (tid < nb) ? g_bsum[tid] : 0;
        x = v;
        #pragma unroll
        for (int d = 1; d < 32; d <<= 1) {
            int n = __shfl_up_sync(0xffffffff, x, d);
            if (lane >= d) x += n;
        }
        if (lane == 31) wtot[w] = x;
    }
    __syncthreads();
    if (tid == 0) {
        int a = 0;
        #pragma unroll
        for (int j = 0; j < 4; j++) { int t = wtot[j]; wtot[j] = a; a += t; }
    }
    __syncthreads();
    if (tid < 128) sbase[tid] = wtot[w] + x - v;   // exclusive base per scan block
    __syncthreads();
    int i = blockIdx.x * blockDim.x + tid;
    if (i < NN) {
        int o = g_off[i] + sbase[i >> 10];
        g_off[i] = o;
        g_cur[i] = o;
        g_dis[i] = rsqrtf((float)(g_cnt[i] + 1));
        if (i == 0) g_off[NN] = EE;
    }
}

// ---------------- CSR fill ----------------------------------------------------
__global__ void k_fill(const int* __restrict__ ei) {
    int e = blockIdx.x * blockDim.x + threadIdx.x;
    if (e >= EE) return;
    int s = ei[e];
    int d = ei[EE + e];
    int pos = atomicAdd(&g_cur[d], 1);
    g_srcs[pos] = s;
}

// ---- transform: g_t(half) = dis[r] * ([BN+ReLU](src[r]) @ W + b) -------------
// MODE 0: src = x (input pointer), no BN.  MODE 1: src = g_h, fused BN+ReLU
// (BN mu/istd derived in-kernel from g_bn sums — no separate finalize launch).
// 4 rows per warp: each W LDS.64 feeds 8 FFMAs (amortizes shared traffic 4x).
template <int MODE>
__global__ void k_gemm(const float* __restrict__ in, const float* __restrict__ W,
                       const float* __restrict__ bias,
                       const float* __restrict__ gamma, const float* __restrict__ beta) {
    __shared__ __align__(16) float Wsh[64 * 64];
    __shared__ float bsh[64];
    __shared__ float xsh[8][4][64];
    int tid = threadIdx.x;
    for (int i = tid; i < 4096; i += 256) Wsh[i] = W[i];
    if (tid < 64) bsh[tid] = bias[tid];
    int warp = tid >> 5, lane = tid & 31;
    int c0 = 2 * lane, c1 = c0 + 1;
    float a0 = 1.f, s0 = 0.f, a1 = 1.f, s1 = 0.f;
    if (MODE == 1) {
        const float invn = 1.0f / NN;
        float mu0 = g_bn[c0] * invn, mu1 = g_bn[c1] * invn;
        float var0 = g_bn[64 + c0] * invn - mu0 * mu0;
        float var1 = g_bn[64 + c1] * invn - mu1 * mu1;
        a0 = rsqrtf(var0 + BN_EPS) * gamma[c0];
        a1 = rsqrtf(var1 + BN_EPS) * gamma[c1];
        s0 = beta[c0] - mu0 * a0;
        s1 = beta[c1] - mu1 * a1;
    }
    __syncthreads();
    const float* __restrict__ src = (MODE == 1) ? (const float*)g_h : in;
    __half2* outp = (__half2*)g_t;
    int r0 = blockIdx.x * 32 + warp * 4;           // 3125 blocks * 32 rows = NN exactly
    #pragma unroll
    for (int i = 0; i < 4; i++) {
        float2 xv = *(const float2*)(src + (size_t)(r0 + i) * 64 + c0);
        if (MODE == 1) {
            xv.x = fmaxf(fmaf(xv.x, a0, s0), 0.f);
            xv.y = fmaxf(fmaf(xv.y, a1, s1), 0.f);
        }
        xsh[warp][i][c0] = xv.x;
        xsh[warp][i][c1] = xv.y;
    }
    __syncwarp();
    float ax[4], ay[4];
    #pragma unroll
    for (int i = 0; i < 4; i++) { ax[i] = bsh[c0]; ay[i] = bsh[c1]; }
    #pragma unroll 16
    for (int k = 0; k < 64; k++) {
        float2 w = *(const float2*)&Wsh[k * 64 + c0];
        #pragma unroll
        for (int i = 0; i < 4; i++) {
            float xk = xsh[warp][i][k];
            ax[i] += xk * w.x;
            ay[i] += xk * w.y;
        }
    }
    #pragma unroll
    for (int i = 0; i < 4; i++) {
        float dv = g_dis[r0 + i];
        outp[(size_t)(r0 + i) * 32 + lane] = __floats2half2_rn(ax[i] * dv, ay[i] * dv);
    }
}

// ---- aggregate: out[v] = dis[v] * (sum_{s in nbrs} t'[s] + t'[v]) ------------
// (dis[s] is pre-folded into t', so no per-edge weight loads.)
__device__ __forceinline__ void agg_row(int v, int lane, float& sx, float& sy) {
    const __half2* __restrict__ t = (const __half2*)g_t;
    float2 self = __half22float2(t[(size_t)v * 32 + lane]);
    sx = self.x; sy = self.y;
    int beg = g_off[v], end = g_off[v + 1];
    int e = beg;
    for (; e + 4 <= end; e += 4) {
        int s0 = g_srcs[e], s1 = g_srcs[e + 1], s2 = g_srcs[e + 2], s3 = g_srcs[e + 3];
        float2 a0 = __half22float2(t[(size_t)s0 * 32 + lane]);
        float2 a1 = __half22float2(t[(size_t)s1 * 32 + lane]);
        float2 a2 = __half22float2(t[(size_t)s2 * 32 + lane]);
        float2 a3 = __half22float2(t[(size_t)s3 * 32 + lane]);
        sx += a0.x + a1.x + a2.x + a3.x;
        sy += a0.y + a1.y + a2.y + a3.y;
    }
    for (; e < end; e++) {
        int s = g_srcs[e];
        float2 a = __half22float2(t[(size_t)s * 32 + lane]);
        sx += a.x;
        sy += a.y;
    }
    float dv = g_dis[v];
    sx *= dv;
    sy *= dv;
}

// conv1 aggregate: write g_h AND accumulate BN statistics (fused)
__global__ void k_agg_bnstats() {
    __shared__ float ssum[8][64];
    __shared__ float ssq[8][64];
    int tid = threadIdx.x;
    int warp = tid >> 5, lane = tid & 31;
    int v = blockIdx.x * 8 + warp;
    int c0 = 2 * lane, c1 = c0 + 1;
    float sx = 0.f, sy = 0.f;
    if (v < NN) {
        agg_row(v, lane, sx, sy);
        *(float2*)(g_h + (size_t)v * 64 + c0) = make_float2(sx, sy);
    }
    ssum[warp][c0] = sx;  ssum[warp][c1] = sy;
    ssq[warp][c0] = sx * sx;  ssq[warp][c1] = sy * sy;
    __syncthreads();
    if (tid < 64) {
        float s = 0.f, q = 0.f;
        #pragma unroll
        for (int w = 0; w < 8; w++) { s += ssum[w][tid]; q += ssq[w][tid]; }
        atomicAdd(&g_bn[tid], s);
        atomicAdd(&g_bn[64 + tid], q);
    }
}

// conv2 aggregate fused with per-graph mean pooling.
// batch is sorted -> consecutive nodes mostly share a graph: pre-reduce runs
// in shared memory, emit one atomic per (distinct graph, column) per block.
__global__ void k_agg_pool(const int* __restrict__ batch) {
    __shared__ float vals[8][64];
    __shared__ int gids[8];
    int tid = threadIdx.x;
    int warp = tid >> 5, lane = tid & 31;
    int v = blockIdx.x * 8 + warp;
    float sx = 0.f, sy = 0.f;
    int g = -1;
    if (v < NN) {
        agg_row(v, lane, sx, sy);
        g = batch[v];
    }
    vals[warp][2 * lane] = sx;
    vals[warp][2 * lane + 1] = sy;
    if (lane == 0) gids[warp] = g;
    __syncthreads();
    if (tid < 64) {
        int c = tid;
        float acc = 0.f;
        int cur = -1;
        #pragma unroll
        for (int w = 0; w < 8; w++) {
            int gw = gids[w];
            if (gw < 0) continue;
            if (gw != cur) {
                if (cur >= 0) atomicAdd(&g_gsum[cur * 64 + c], acc);
                cur = gw;
                acc = 0.f;
            }
            acc += vals[w][c];
        }
        if (cur >= 0) atomicAdd(&g_gsum[cur * 64 + c], acc);
    } else if (tid == 64) {
        float cnt = 0.f;
        int cur = -1;
        #pragma unroll
        for (int w = 0; w < 8; w++) {
            int gw = gids[w];
            if (gw < 0) continue;
            if (gw != cur) {
                if (cur >= 0) atomicAdd(&g_gcnt[cur], cnt);
                cur = gw;
                cnt = 0.f;
            }
            cnt += 1.f;
        }
        if (cur >= 0) atomicAdd(&g_gcnt[cur], cnt);
    }
}

// ---------------- graph-level: pool finalize + L2 norm + Wc1 ------------------
__global__ void k_graph1(const float* __restrict__ Wc1, const float* __restrict__ bc1,
                         float* __restrict__ rep_out) {
    __shared__ __align__(16) float Wsh[64 * 64];
    __shared__ float bsh[64];
    __shared__ float xsh[8][64];
    int tid = threadIdx.x;
    for (int i = tid; i < 4096; i += 256) Wsh[i] = Wc1[i];
    if (tid < 64) bsh[tid] = bc1[tid];
    __syncthreads();
    int warp = tid >> 5, lane = tid & 31;
    int g = blockIdx.x * 8 + warp;
    if (g >= GG) return;
    float cnt = fmaxf(g_gcnt[g], 1.0f);
    float mx = g_gsum[g * 64 + 2 * lane] / cnt;
    float my = g_gsum[g * 64 + 2 * lane + 1] / cnt;
    float ss = mx * mx + my * my;
    #pragma unroll
    for (int o = 16; o > 0; o >>= 1) ss += __shfl_xor_sync(0xffffffff, ss, o);
    float inv = rsqrtf(ss);
    mx *= inv; my *= inv;
    rep_out[g * 64 + 2 * lane] = mx;
    rep_out[g * 64 + 2 * lane + 1] = my;
    xsh[warp][2 * lane] = mx;
    xsh[warp][2 * lane + 1] = my;
    __syncwarp();
    float ax = bsh[2 * lane], ay = bsh[2 * lane + 1];
    #pragma unroll
    for (int k = 0; k < 64; k++) {
        float xk = xsh[warp][k];
        float2 w = *(const float2*)&Wsh[k * 64 + 2 * lane];
        ax += xk * w.x;
        ay += xk * w.y;
    }
    g_z1[g * 64 + 2 * lane] = ax;
    g_z1[g * 64 + 2 * lane + 1] = ay;
    atomicAdd(&g_cbn[2 * lane], ax);
    atomicAdd(&g_cbn[2 * lane + 1], ay);
    atomicAdd(&g_cbn[64 + 2 * lane], ax * ax);
    atomicAdd(&g_cbn[64 + 2 * lane + 1], ay * ay);
}

// ---- classifier tail: BN(finalized in-kernel)+ReLU -> Wc2 -> log_softmax -----
__global__ void k_graph2(const float* __restrict__ Wc2, const float* __restrict__ bc2,
                         const float* __restrict__ gammac, const float* __restrict__ betac,
                         float* __restrict__ pred_out) {
    __shared__ float Wsh[64 * 10];
    __shared__ float xsh[8][64];
    int tid = threadIdx.x;
    for (int i = tid; i < 640; i += 256) Wsh[i] = Wc2[i];
    __syncthreads();
    int warp = tid >> 5, lane = tid & 31;
    int g = blockIdx.x * 8 + warp;
    if (g >= GG) return;
    int c0 = 2 * lane, c1 = 2 * lane + 1;
    const float invg = 1.0f / GG;
    float mu0 = g_cbn[c0] * invg, mu1 = g_cbn[c1] * invg;
    float var0 = g_cbn[64 + c0] * invg - mu0 * mu0;
    float var1 = g_cbn[64 + c1] * invg - mu1 * mu1;
    float is0 = rsqrtf(var0 + BN_EPS), is1 = rsqrtf(var1 + BN_EPS);
    float z0 = g_z1[g * 64 + c0];
    float z1v = g_z1[g * 64 + c1];
    z0 = fmaxf((z0 - mu0) * is0 * gammac[c0] + betac[c0], 0.f);
    z1v = fmaxf((z1v - mu1) * is1 * gammac[c1] + betac[c1], 0.f);
    xsh[warp][c0] = z0;
    xsh[warp][c1] = z1v;
    __syncwarp();
    bool valid = (lane < CC);
    float acc = valid ? bc2[lane] : 0.f;
    if (valid) {
        #pragma unroll
        for (int k = 0; k < 64; k++) acc += xsh[warp][k] * Wsh[k * 10 + lane];
    }
    float v = valid ? acc : -1e30f;
    float m = v;
    #pragma unroll
    for (int o = 16; o > 0; o >>= 1) m = fmaxf(m, __shfl_xor_sync(0xffffffff, m, o));
    float ex = valid ? __expf(v - m) : 0.f;
    float s = ex;
    #pragma unroll
    for (int o = 16; o > 0; o >>= 1) s += __shfl_xor_sync(0xffffffff, s, o);
    if (valid) pred_out[g * CC + lane] = v - m - logf(s);
}

// ---------------- launch ------------------------------------------------------
extern "C" void kernel_launch(void* const* d_in, const int* in_sizes, int n_in,
                              void* d_out, int out_size) {
    const float* x     = (const float*)d_in[0];
    const int*   ei    = (const int*)d_in[1];    // int32 (JAX x64 disabled)
    const int*   batch = (const int*)d_in[2];    // int32
    const float* W1    = (const float*)d_in[3];
    const float* b1    = (const float*)d_in[4];
    const float* gamma1= (const float*)d_in[5];
    const float* beta1 = (const float*)d_in[6];
    const float* W2    = (const float*)d_in[7];
    const float* b2    = (const float*)d_in[8];
    const float* Wc1   = (const float*)d_in[9];
    const float* bc1   = (const float*)d_in[10];
    const float* gammac= (const float*)d_in[11];
    const float* betac = (const float*)d_in[12];
    const float* Wc2   = (const float*)d_in[13];
    const float* bc2   = (const float*)d_in[14];

    float* out  = (float*)d_out;
    float* pred = out;              // [G, 10]
    float* rep  = out + GG * CC;    // [G, 64]

    const int nb_scan = (NN + 1023) / 1024;  // 98

    k_zero<<<(NN + 255) / 256, 256>>>();
    k_degree<<<(EE + 255) / 256, 256>>>(ei);
    k_scan_block<<<nb_scan, 1024>>>();
    k_scan_add<<<(NN + 255) / 256, 256>>>(nb_scan);
    k_fill<<<(EE + 255) / 256, 256>>>(ei);

    // conv1: transform (dis-scaled fp16 out) -> aggregate + BN stats
    k_gemm<0><<<NN / 32, 256>>>(x, W1, b1, nullptr, nullptr);
    k_agg_bnstats<<<(NN + 7) / 8, 256>>>();

    // conv2: BN+ReLU fused into transform (BN finalize in-kernel) -> agg+pool
    k_gemm<1><<<NN / 32, 256>>>(nullptr, W2, b2, gamma1, beta1);
    k_agg_pool<<<(NN + 7) / 8, 256>>>(batch);

    // classifier
    k_graph1<<<(GG + 7) / 8, 256>>>(Wc1, bc1, rep);
    k_graph2<<<(GG + 7) / 8, 256>>>(Wc2, bc2, gammac, betac, pred);
}

// round 8
// speedup vs baseline: 1.5159x; 1.0841x over previous
#include <cuda_runtime.h>
#include <cuda_fp16.h>
#include <math.h>
#include <stdint.h>

#define NN 100000
#define EE 1600000
#define GG 1000
#define HH 64
#define CC 10
#define BN_EPS 1e-5f
#define SP 66   // padded smem row stride in halves (33 words -> conflict-free)

// ---------------- scratch (static device memory; no allocation at runtime) ----
__device__ __align__(16) int    g_cnt[NN];
__device__ __align__(16) int    g_off[NN + 1];
__device__ __align__(16) int    g_cur[NN];
__device__ __align__(16) int    g_srcs[EE];
__device__ __align__(16) float  g_dis[NN];
__device__ __align__(16) __half g_t[NN * HH];     // dis-scaled transformed features
__device__ __align__(16) float  g_h[NN * HH];     // conv1 output
__device__ __align__(16) float  g_bn[128];        // [0:64] sum, [64:128] sumsq
__device__ __align__(16) float  g_cbn[128];
__device__ __align__(16) float  g_gsum[GG * HH];
__device__ __align__(16) float  g_gcnt[GG];
__device__ __align__(16) float  g_z1[GG * HH];
__device__ __align__(16) int    g_bsum[128];

// ---------------- zero scratch ------------------------------------------------
__global__ void k_zero() {
    int i = blockIdx.x * blockDim.x + threadIdx.x;
    if (i < NN) g_cnt[i] = 0;
    if (i < 128) { g_bn[i] = 0.f; g_cbn[i] = 0.f; }
    if (i < GG * HH) g_gsum[i] = 0.f;
    if (i < GG) g_gcnt[i] = 0.f;
}

// ---------------- degree count ------------------------------------------------
__global__ void k_degree(const int* __restrict__ ei) {
    int e = blockIdx.x * blockDim.x + threadIdx.x;
    if (e >= EE) return;
    atomicAdd(&g_cnt[ei[EE + e]], 1);
}

// ---------------- block-level exclusive scan of g_cnt -------------------------
__global__ void k_scan_block() {
    __shared__ int wsum[32];
    int tid = threadIdx.x;
    int lane = tid & 31, warp = tid >> 5;
    int i = blockIdx.x * 1024 + tid;
    int v = (i < NN) ? g_cnt[i] : 0;
    int x = v;
    #pragma unroll
    for (int d = 1; d < 32; d <<= 1) {
        int n = __shfl_up_sync(0xffffffff, x, d);
        if (lane >= d) x += n;
    }
    if (lane == 31) wsum[warp] = x;
    __syncthreads();
    if (warp == 0) {
        int y = wsum[lane];
        #pragma unroll
        for (int d = 1; d < 32; d <<= 1) {
            int n = __shfl_up_sync(0xffffffff, y, d);
            if (lane >= d) y += n;
        }
        wsum[lane] = y;
    }
    __syncthreads();
    int base = warp ? wsum[warp - 1] : 0;
    int incl = base + x;
    if (i < NN) g_off[i] = incl - v;
    if (tid == 1023) g_bsum[blockIdx.x] = incl;
}

// ---- finalize offsets: each block redundantly scans the 98 block sums --------
__global__ void k_scan_add(int nb) {
    __shared__ int sbase[128];
    __shared__ int wtot[4];
    int tid = threadIdx.x;
    int lane = tid & 31, w = tid >> 5;
    int v = 0, x = 0;
    if (tid < 128) {
        v = (tid < nb) ? g_bsum[tid] : 0;
        x = v;
        #pragma unroll
        for (int d = 1; d < 32; d <<= 1) {
            int n = __shfl_up_sync(0xffffffff, x, d);
            if (lane >= d) x += n;
        }
        if (lane == 31) wtot[w] = x;
    }
    __syncthreads();
    if (tid == 0) {
        int a = 0;
        #pragma unroll
        for (int j = 0; j < 4; j++) { int t = wtot[j]; wtot[j] = a; a += t; }
    }
    __syncthreads();
    if (tid < 128) sbase[tid] = wtot[w] + x - v;
    __syncthreads();
    int i = blockIdx.x * blockDim.x + tid;
    if (i < NN) {
        int o = g_off[i] + sbase[i >> 10];
        g_off[i] = o;
        g_cur[i] = o;
        g_dis[i] = rsqrtf((float)(g_cnt[i] + 1));
        if (i == 0) g_off[NN] = EE;
    }
}

// ---------------- CSR fill ----------------------------------------------------
__global__ void k_fill(const int* __restrict__ ei) {
    int e = blockIdx.x * blockDim.x + threadIdx.x;
    if (e >= EE) return;
    int s = ei[e];
    int d = ei[EE + e];
    g_srcs[atomicAdd(&g_cur[d], 1)] = s;
}

// ---- tensor-core transform: g_t = dis[r] * ([BN+ReLU](src[r]) @ W + b) -------
// mma.sync.m16n8k16 f16 in / f32 accum. 8 warps x 16 rows = 128 rows/block.
// MODE 0: src = x.  MODE 1: src = g_h with fused BN+ReLU (stats from g_bn sums).
template <int MODE>
__global__ void k_gemm(const float* __restrict__ in, const float* __restrict__ W,
                       const float* __restrict__ bias,
                       const float* __restrict__ gamma, const float* __restrict__ beta) {
    __shared__ __half xs[128 * SP];   // per-warp 16-row staging (fp16)
    __shared__ __half wt[64 * SP];    // W^T: wt[n][k]
    __shared__ float  bsh[64];
    int tid = threadIdx.x;
    int warp = tid >> 5, lane = tid & 31;

    // stage W transposed as fp16 (+ bias)
    for (int i = tid; i < 4096; i += 256) {
        int n = i >> 6, k = i & 63;
        wt[n * SP + k] = __float2half(W[k * 64 + n]);
    }
    if (tid < 64) bsh[tid] = bias[tid];

    // BN folding coefficients for this lane's two columns
    int c0 = 2 * lane, c1 = c0 + 1;
    float a0 = 1.f, s0 = 0.f, a1 = 1.f, s1 = 0.f;
    if (MODE == 1) {
        const float invn = 1.0f / NN;
        float mu0 = g_bn[c0] * invn, mu1 = g_bn[c1] * invn;
        float var0 = g_bn[64 + c0] * invn - mu0 * mu0;
        float var1 = g_bn[64 + c1] * invn - mu1 * mu1;
        a0 = rsqrtf(var0 + BN_EPS) * gamma[c0];
        a1 = rsqrtf(var1 + BN_EPS) * gamma[c1];
        s0 = beta[c0] - mu0 * a0;
        s1 = beta[c1] - mu1 * a1;
    }
    __syncthreads();

    int wrow0 = blockIdx.x * 128 + warp * 16;   // NN % 16 == 0: tiles full or absent
    if (wrow0 >= NN) return;                    // no further block-wide syncs below

    const float* __restrict__ src = (MODE == 1) ? (const float*)g_h : in;
    __half* xw = xs + warp * 16 * SP;

    // load 16 rows into smem as fp16 (BN+ReLU fused for MODE 1)
    #pragma unroll
    for (int r = 0; r < 16; r++) {
        float2 v = *(const float2*)(src + (size_t)(wrow0 + r) * 64 + c0);
        if (MODE == 1) {
            v.x = fmaxf(fmaf(v.x, a0, s0), 0.f);
            v.y = fmaxf(fmaf(v.y, a1, s1), 0.f);
        }
        *(__half2*)&xw[r * SP + c0] = __floats2half2_rn(v.x, v.y);
    }
    __syncwarp();

    int gr = lane >> 2, tg = lane & 3;          // fragment coords
    float acc[8][4];
    #pragma unroll
    for (int nt = 0; nt < 8; nt++) {
        float bx = bsh[nt * 8 + tg * 2], by = bsh[nt * 8 + tg * 2 + 1];
        acc[nt][0] = bx; acc[nt][1] = by; acc[nt][2] = bx; acc[nt][3] = by;
    }
    #pragma unroll
    for (int ks = 0; ks < 4; ks++) {
        int kb = ks * 16 + tg * 2;
        uint32_t fa0 = *(const uint32_t*)&xw[gr * SP + kb];
        uint32_t fa1 = *(const uint32_t*)&xw[(gr + 8) * SP + kb];
        uint32_t fa2 = *(const uint32_t*)&xw[gr * SP + kb + 8];
        uint32_t fa3 = *(const uint32_t*)&xw[(gr + 8) * SP + kb + 8];
        #pragma unroll
        for (int nt = 0; nt < 8; nt++) {
            uint32_t fb0 = *(const uint32_t*)&wt[(nt * 8 + gr) * SP + kb];
            uint32_t fb1 = *(const uint32_t*)&wt[(nt * 8 + gr) * SP + kb + 8];
            asm volatile(
                "mma.sync.aligned.m16n8k16.row.col.f32.f16.f16.f32 "
                "{%0,%1,%2,%3}, {%4,%5,%6,%7}, {%8,%9}, {%0,%1,%2,%3};"
                : "+f"(acc[nt][0]), "+f"(acc[nt][1]), "+f"(acc[nt][2]), "+f"(acc[nt][3])
                : "r"(fa0), "r"(fa1), "r"(fa2), "r"(fa3), "r"(fb0), "r"(fb1));
        }
    }
    // epilogue: scale by dis, restage in smem, coalesced store
    float dv0 = g_dis[wrow0 + gr];
    float dv8 = g_dis[wrow0 + gr + 8];
    __syncwarp();
    #pragma unroll
    for (int nt = 0; nt < 8; nt++) {
        int cc = nt * 8 + tg * 2;
        *(__half2*)&xw[gr * SP + cc]       = __floats2half2_rn(acc[nt][0] * dv0, acc[nt][1] * dv0);
        *(__half2*)&xw[(gr + 8) * SP + cc] = __floats2half2_rn(acc[nt][2] * dv8, acc[nt][3] * dv8);
    }
    __syncwarp();
    uint32_t* gw = (uint32_t*)g_t;
    #pragma unroll
    for (int r = 0; r < 16; r++) {
        gw[(size_t)(wrow0 + r) * 32 + lane] = ((const uint32_t*)&xw[r * SP])[lane];
    }
}

// ---- aggregate: out[v] = dis[v] * (sum_{s in nbrs} t'[s] + t'[v]) ------------
__device__ __forceinline__ void agg_row(int v, int lane, float& sx, float& sy) {
    const __half2* __restrict__ t = (const __half2*)g_t;
    float2 self = __half22float2(t[(size_t)v * 32 + lane]);
    sx = self.x; sy = self.y;
    int e = g_off[v], end = g_off[v + 1];
    for (; e + 8 <= end; e += 8) {
        int s0 = g_srcs[e],     s1 = g_srcs[e + 1], s2 = g_srcs[e + 2], s3 = g_srcs[e + 3];
        int s4 = g_srcs[e + 4], s5 = g_srcs[e + 5], s6 = g_srcs[e + 6], s7 = g_srcs[e + 7];
        float2 a0 = __half22float2(t[(size_t)s0 * 32 + lane]);
        float2 a1 = __half22float2(t[(size_t)s1 * 32 + lane]);
        float2 a2 = __half22float2(t[(size_t)s2 * 32 + lane]);
        float2 a3 = __half22float2(t[(size_t)s3 * 32 + lane]);
        float2 a4 = __half22float2(t[(size_t)s4 * 32 + lane]);
        float2 a5 = __half22float2(t[(size_t)s5 * 32 + lane]);
        float2 a6 = __half22float2(t[(size_t)s6 * 32 + lane]);
        float2 a7 = __half22float2(t[(size_t)s7 * 32 + lane]);
        sx += ((a0.x + a1.x) + (a2.x + a3.x)) + ((a4.x + a5.x) + (a6.x + a7.x));
        sy += ((a0.y + a1.y) + (a2.y + a3.y)) + ((a4.y + a5.y) + (a6.y + a7.y));
    }
    for (; e < end; e++) {
        float2 a = __half22float2(t[(size_t)g_srcs[e] * 32 + lane]);
        sx += a.x;
        sy += a.y;
    }
    float dv = g_dis[v];
    sx *= dv;
    sy *= dv;
}

// conv1 aggregate: write g_h AND accumulate BN statistics (fused)
__global__ void k_agg_bnstats() {
    __shared__ float ssum[8][64];
    __shared__ float ssq[8][64];
    int tid = threadIdx.x;
    int warp = tid >> 5, lane = tid & 31;
    int v = blockIdx.x * 8 + warp;
    int c0 = 2 * lane, c1 = c0 + 1;
    float sx = 0.f, sy = 0.f;
    if (v < NN) {
        agg_row(v, lane, sx, sy);
        *(float2*)(g_h + (size_t)v * 64 + c0) = make_float2(sx, sy);
    }
    ssum[warp][c0] = sx;  ssum[warp][c1] = sy;
    ssq[warp][c0] = sx * sx;  ssq[warp][c1] = sy * sy;
    __syncthreads();
    if (tid < 64) {
        float s = 0.f, q = 0.f;
        #pragma unroll
        for (int w = 0; w < 8; w++) { s += ssum[w][tid]; q += ssq[w][tid]; }
        atomicAdd(&g_bn[tid], s);
        atomicAdd(&g_bn[64 + tid], q);
    }
}

// conv2 aggregate fused with per-graph mean pooling (batch sorted -> run dedup)
__global__ void k_agg_pool(const int* __restrict__ batch) {
    __shared__ float vals[8][64];
    __shared__ int gids[8];
    int tid = threadIdx.x;
    int warp = tid >> 5, lane = tid & 31;
    int v = blockIdx.x * 8 + warp;
    float sx = 0.f, sy = 0.f;
    int g = -1;
    if (v < NN) {
        agg_row(v, lane, sx, sy);
        g = batch[v];
    }
    vals[warp][2 * lane] = sx;
    vals[warp][2 * lane + 1] = sy;
    if (lane == 0) gids[warp] = g;
    __syncthreads();
    if (tid < 64) {
        int c = tid;
        float acc = 0.f;
        int cur = -1;
        #pragma unroll
        for (int w = 0; w < 8; w++) {
            int gw = gids[w];
            if (gw < 0) continue;
            if (gw != cur) {
                if (cur >= 0) atomicAdd(&g_gsum[cur * 64 + c], acc);
                cur = gw;
                acc = 0.f;
            }
            acc += vals[w][c];
        }
        if (cur >= 0) atomicAdd(&g_gsum[cur * 64 + c], acc);
    } else if (tid == 64) {
        float cnt = 0.f;
        int cur = -1;
        #pragma unroll
        for (int w = 0; w < 8; w++) {
            int gw = gids[w];
            if (gw < 0) continue;
            if (gw != cur) {
                if (cur >= 0) atomicAdd(&g_gcnt[cur], cnt);
                cur = gw;
                cnt = 0.f;
            }
            cnt += 1.f;
        }
        if (cur >= 0) atomicAdd(&g_gcnt[cur], cnt);
    }
}

// ---------------- graph-level: pool finalize + L2 norm + Wc1 ------------------
__global__ void k_graph1(const float* __restrict__ Wc1, const float* __restrict__ bc1,
                         float* __restrict__ rep_out) {
    __shared__ __align__(16) float Wsh[64 * 64];
    __shared__ float bsh[64];
    __shared__ float xsh[8][64];
    int tid = threadIdx.x;
    for (int i = tid; i < 4096; i += 256) Wsh[i] = Wc1[i];
    if (tid < 64) bsh[tid] = bc1[tid];
    __syncthreads();
    int warp = tid >> 5, lane = tid & 31;
    int g = blockIdx.x * 8 + warp;
    if (g >= GG) return;
    float cnt = fmaxf(g_gcnt[g], 1.0f);
    float mx = g_gsum[g * 64 + 2 * lane] / cnt;
    float my = g_gsum[g * 64 + 2 * lane + 1] / cnt;
    float ss = mx * mx + my * my;
    #pragma unroll
    for (int o = 16; o > 0; o >>= 1) ss += __shfl_xor_sync(0xffffffff, ss, o);
    float inv = rsqrtf(ss);
    mx *= inv; my *= inv;
    rep_out[g * 64 + 2 * lane] = mx;
    rep_out[g * 64 + 2 * lane + 1] = my;
    xsh[warp][2 * lane] = mx;
    xsh[warp][2 * lane + 1] = my;
    __syncwarp();
    float ax = bsh[2 * lane], ay = bsh[2 * lane + 1];
    #pragma unroll
    for (int k = 0; k < 64; k++) {
        float xk = xsh[warp][k];
        float2 w = *(const float2*)&Wsh[k * 64 + 2 * lane];
        ax += xk * w.x;
        ay += xk * w.y;
    }
    g_z1[g * 64 + 2 * lane] = ax;
    g_z1[g * 64 + 2 * lane + 1] = ay;
    atomicAdd(&g_cbn[2 * lane], ax);
    atomicAdd(&g_cbn[2 * lane + 1], ay);
    atomicAdd(&g_cbn[64 + 2 * lane], ax * ax);
    atomicAdd(&g_cbn[64 + 2 * lane + 1], ay * ay);
}

// ---- classifier tail: BN(finalized in-kernel)+ReLU -> Wc2 -> log_softmax -----
__global__ void k_graph2(const float* __restrict__ Wc2, const float* __restrict__ bc2,
                         const float* __restrict__ gammac, const float* __restrict__ betac,
                         float* __restrict__ pred_out) {
    __shared__ float Wsh[64 * 10];
    __shared__ float xsh[8][64];
    int tid = threadIdx.x;
    for (int i = tid; i < 640; i += 256) Wsh[i] = Wc2[i];
    __syncthreads();
    int warp = tid >> 5, lane = tid & 31;
    int g = blockIdx.x * 8 + warp;
    if (g >= GG) return;
    int c0 = 2 * lane, c1 = 2 * lane + 1;
    const float invg = 1.0f / GG;
    float mu0 = g_cbn[c0] * invg, mu1 = g_cbn[c1] * invg;
    float var0 = g_cbn[64 + c0] * invg - mu0 * mu0;
    float var1 = g_cbn[64 + c1] * invg - mu1 * mu1;
    float is0 = rsqrtf(var0 + BN_EPS), is1 = rsqrtf(var1 + BN_EPS);
    float z0 = g_z1[g * 64 + c0];
    float z1v = g_z1[g * 64 + c1];
    z0 = fmaxf((z0 - mu0) * is0 * gammac[c0] + betac[c0], 0.f);
    z1v = fmaxf((z1v - mu1) * is1 * gammac[c1] + betac[c1], 0.f);
    xsh[warp][c0] = z0;
    xsh[warp][c1] = z1v;
    __syncwarp();
    bool valid = (lane < CC);
    float acc = valid ? bc2[lane] : 0.f;
    if (valid) {
        #pragma unroll
        for (int k = 0; k < 64; k++) acc += xsh[warp][k] * Wsh[k * 10 + lane];
    }
    float v = valid ? acc : -1e30f;
    float m = v;
    #pragma unroll
    for (int o = 16; o > 0; o >>= 1) m = fmaxf(m, __shfl_xor_sync(0xffffffff, m, o));
    float ex = valid ? __expf(v - m) : 0.f;
    float s = ex;
    #pragma unroll
    for (int o = 16; o > 0; o >>= 1) s += __shfl_xor_sync(0xffffffff, s, o);
    if (valid) pred_out[g * CC + lane] = v - m - logf(s);
}

// ---------------- launch ------------------------------------------------------
extern "C" void kernel_launch(void* const* d_in, const int* in_sizes, int n_in,
                              void* d_out, int out_size) {
    const float* x     = (const float*)d_in[0];
    const int*   ei    = (const int*)d_in[1];    // int32 (JAX x64 disabled)
    const int*   batch = (const int*)d_in[2];    // int32
    const float* W1    = (const float*)d_in[3];
    const float* b1    = (const float*)d_in[4];
    const float* gamma1= (const float*)d_in[5];
    const float* beta1 = (const float*)d_in[6];
    const float* W2    = (const float*)d_in[7];
    const float* b2    = (const float*)d_in[8];
    const float* Wc1   = (const float*)d_in[9];
    const float* bc1   = (const float*)d_in[10];
    const float* gammac= (const float*)d_in[11];
    const float* betac = (const float*)d_in[12];
    const float* Wc2   = (const float*)d_in[13];
    const float* bc2   = (const float*)d_in[14];

    float* out  = (float*)d_out;
    float* pred = out;              // [G, 10]
    float* rep  = out + GG * CC;    // [G, 64]

    const int nb_scan = (NN + 1023) / 1024;  // 98
    const int nb_gemm = (NN + 127) / 128;    // 782

    k_zero<<<(NN + 255) / 256, 256>>>();
    k_degree<<<(EE + 255) / 256, 256>>>(ei);
    k_scan_block<<<nb_scan, 1024>>>();
    k_scan_add<<<(NN + 255) / 256, 256>>>(nb_scan);
    k_fill<<<(EE + 255) / 256, 256>>>(ei);

    // conv1: tensor-core transform -> aggregate + BN stats
    k_gemm<0><<<nb_gemm, 256>>>(x, W1, b1, nullptr, nullptr);
    k_agg_bnstats<<<(NN + 7) / 8, 256>>>();

    // conv2: BN+ReLU fused into tensor-core transform -> aggregate + pooling
    k_gemm<1><<<nb_gemm, 256>>>(nullptr, W2, b2, gamma1, beta1);
    k_agg_pool<<<(NN + 7) / 8, 256>>>(batch);

    // classifier
    k_graph1<<<(GG + 7) / 8, 256>>>(Wc1, bc1, rep);
    k_graph2<<<(GG + 7) / 8, 256>>>(Wc2, bc2, gammac, betac, pred);
}